// round 17
// baseline (speedup 1.0000x reference)
#include <cuda_runtime.h>
#include <cuda_bf16.h>
#include <cstddef>

// Soft-Viterbi DP (N=M=2048, 3 states m,x,y) in LINEAR space with per-thread
// power-of-2 scaling: E = exp(V - K*ln2); lse3 -> FFMA dot products.
// Boundary V=-1e8 -> exactly 0. Output: K*ln2 + log(em+ex+ey).
// (Math validated R9-R16: rel_err 3.3e-6.)
//
// R17: single-CTA skewed systolic, TWO ROWS PER BARRIER STEP.
//  - TT=256 threads (8 warps), C=8 columns/thread. At step s, thread t
//    computes rows i0=2(s-t)+1 and i1=i0+1 for its columns. 1279 steps,
//    ONE __syncthreads per step (half of R13's barrier count).
//  - Strip edges (last column of each thread, rows i0 & i1, + scale K)
//    cross threads via 3-slot rotating SMEM float4 buffers eA/eB.
//    Step s writes slot s%3; reads t-1's slots (s-1)%3 (rows i0,i1) and
//    (s-2)%3 (row i0-1, the diag). Zero-init slots = row-0 semantics.
//  - exp(theta) precomputed chip-wide into 6 float4 planes indexed by
//    (row, thread) -> every DP theta load is lane-contiguous LDG.128.
//  - Renorm once per step (2 rows of growth <= 2^28: safe in fp32).

#define NN 2048
#define MM 2048
#define TT 256
#define C  8
#define QSTEPS (NN / 2 + TT - 1)   // 1279

static_assert(TT * C == MM, "column coverage");

// 6 planes x NN*TT float4 = 50.3 MB scratch (L2-resident on replays).
__device__ float4 g_eth[6][(size_t)NN * TT];

__device__ __forceinline__ float exp2i(int n) {  // 2^n, clamped to normals
    n = max(-126, min(127, n));
    return __int_as_float((n + 127) << 23);
}

// exp(theta) + plane relayout: the 24 floats of (row r, cols 8t..8t+7) are
// 6 consecutive float4s at source index gid*6 (gid = (r-1)*TT + t); plane q
// gets part q -> DP loads are lane-contiguous per plane.
__global__ void eth_kernel(const float* __restrict__ theta) {
    const size_t gid = (size_t)blockIdx.x * blockDim.x + threadIdx.x;
    const float4* t4 = reinterpret_cast<const float4*>(theta);
#pragma unroll
    for (int q = 0; q < 6; ++q) {
        float4 v = t4[gid * 6 + q];
        g_eth[q][gid] = make_float4(__expf(v.x), __expf(v.y),
                                    __expf(v.z), __expf(v.w));
    }
}

__global__ __launch_bounds__(TT, 1)
void ViterbiDecoder_5506148073875_kernel(const float* __restrict__ A,
                                         float* __restrict__ out) {
    __shared__ float4 eA[3][TT];   // edge of first row (i0) of each step
    __shared__ float4 eB[3][TT];   // edge of second row (i1) of each step

    const int t = threadIdx.x;

    const float ea00 = __expf(A[0]), ea01 = __expf(A[1]), ea02 = __expf(A[2]);
    const float ea10 = __expf(A[3]), ea11 = __expf(A[4]), ea12 = __expf(A[5]);
    const float ea20 = __expf(A[6]), ea21 = __expf(A[7]), ea22 = __expf(A[8]);

    // Previous-row state (24 = 8 cells x {m,x,y}), own scale K.
    float p[24];
#pragma unroll
    for (int k = 0; k < 24; ++k) p[k] = 0.f;   // row 0: V=-inf -> 0
    int K = 0;

    // Zero-init all edge slots (value 0, K bits 0): row-0 / unwritten reads.
#pragma unroll
    for (int sl = 0; sl < 3; ++sl) {
        eA[sl][t] = make_float4(0.f, 0.f, 0.f, 0.f);
        eB[sl][t] = make_float4(0.f, 0.f, 0.f, 0.f);
    }

    // Theta pipeline: cur0 = exp(theta) row i0 (preloaded row 1); fut0 = row
    // i0+2 (next step); cur1 = row i1 (loaded at step top, consumed mid-step).
    float4 cur0[6], fut0[6], cur1[6];
#pragma unroll
    for (int q = 0; q < 6; ++q) cur0[q] = g_eth[q][t];   // row 1
    __syncthreads();

    for (int s = 0; s < QSTEPS; ++s) {
        const int i0 = 2 * (s - t) + 1;           // first row this step (odd)
        const bool act = (i0 >= 1 && i0 <= NN - 1);

        // Issue theta loads early (L2 latency hidden under the step's math).
        const int rnext = i0 + 2;                 // next step's first row
        const bool ldf = (rnext >= 3 && rnext <= NN - 1);
        if (ldf) {
            const size_t b = (size_t)(rnext - 1) * TT + t;
#pragma unroll
            for (int q = 0; q < 6; ++q) fut0[q] = g_eth[q][b];
        }
        if (act) {
            const size_t b = (size_t)i0 * TT + t;  // row i1 = i0+1
#pragma unroll
            for (int q = 0; q < 6; ++q) cur1[q] = g_eth[q][b];
        }

        if (act) {
            // Neighbor edges: l0 = row i0, l1 = row i1 (slot s-1);
            // d0 = row i0-1 (slot s-2, second row of that step).
            float4 pl0, pl1, pd0;
            if (t == 0) {
                pl0 = make_float4(0.f, 0.f, 0.f, 0.f);   // V[i,0] = -inf
                pl1 = make_float4(0.f, 0.f, 0.f, 0.f);
                pd0 = (i0 == 1) ? make_float4(1.f, 0.f, 0.f, 0.f)  // V[0,0]
                                : make_float4(0.f, 0.f, 0.f, 0.f);
            } else {
                pl0 = eA[(s + 2) % 3][t - 1];
                pl1 = eB[(s + 2) % 3][t - 1];
                pd0 = eB[(s + 1) % 3][t - 1];
            }
            // Align edge packets to own scale K.
            const float fl0 = exp2i(__float_as_int(pl0.w) - K);
            const float fl1 = exp2i(__float_as_int(pl1.w) - K);
            const float fd0 = exp2i(__float_as_int(pd0.w) - K);
            const float lm0 = pl0.x * fl0, lx0 = pl0.y * fl0, ly0 = pl0.z * fl0;
            const float lm1 = pl1.x * fl1, lx1 = pl1.y * fl1, ly1 = pl1.z * fl1;
            const float dm0 = pd0.x * fd0, dx0 = pd0.y * fd0, dy0 = pd0.z * fd0;

            const float th1[24] = {cur0[0].x, cur0[0].y, cur0[0].z, cur0[0].w,
                                   cur0[1].x, cur0[1].y, cur0[1].z, cur0[1].w,
                                   cur0[2].x, cur0[2].y, cur0[2].z, cur0[2].w,
                                   cur0[3].x, cur0[3].y, cur0[3].z, cur0[3].w,
                                   cur0[4].x, cur0[4].y, cur0[4].z, cur0[4].w,
                                   cur0[5].x, cur0[5].y, cur0[5].z, cur0[5].w};
            const float th2[24] = {cur1[0].x, cur1[0].y, cur1[0].z, cur1[0].w,
                                   cur1[1].x, cur1[1].y, cur1[1].z, cur1[1].w,
                                   cur1[2].x, cur1[2].y, cur1[2].z, cur1[2].w,
                                   cur1[3].x, cur1[3].y, cur1[3].z, cur1[3].w,
                                   cur1[4].x, cur1[4].y, cur1[4].z, cur1[4].w,
                                   cur1[5].x, cur1[5].y, cur1[5].z, cur1[5].w};

            auto do_row = [&](const float* src, const float* th,
                              float dm, float dx, float dy,
                              float lm, float lx, float ly, float* dst) {
#pragma unroll
                for (int c = 0; c < C; ++c) {
                    const float cdm = (c == 0) ? dm : src[3*c - 3];  // diag
                    const float cdx = (c == 0) ? dx : src[3*c - 2];
                    const float cdy = (c == 0) ? dy : src[3*c - 1];
                    const float clm = (c == 0) ? lm : dst[3*c - 3];  // left
                    const float clx = (c == 0) ? lx : dst[3*c - 2];
                    const float cly = (c == 0) ? ly : dst[3*c - 1];
                    dst[3*c + 0] = th[3*c + 0] *
                        fmaf(cdm, ea00, fmaf(cdx, ea01, cdy * ea02));
                    dst[3*c + 1] = th[3*c + 1] *
                        fmaf(src[3*c], ea10,
                             fmaf(src[3*c + 1], ea11, src[3*c + 2] * ea12));
                    dst[3*c + 2] = th[3*c + 2] *
                        fmaf(clm, ea20, fmaf(clx, ea21, cly * ea22));
                }
            };

            float n1[24];
            // Row i0: prev row = p; diag = d0; left = l0.
            do_row(p, th1, dm0, dx0, dy0, lm0, lx0, ly0, n1);
            // Row i1: prev row = n1; diag(cell0) = l0 (V[i0, col-left]);
            // left = l1. Result overwrites p (becomes next step's prev row).
            do_row(n1, th2, lm0, lx0, ly0, lm1, lx1, ly1, p);

            // Renorm once per step using row-i1 max; bump K.
            float g0 = fmaxf(fmaxf(p[0],  p[1]),  fmaxf(p[2],  p[3]));
            float g1 = fmaxf(fmaxf(p[4],  p[5]),  fmaxf(p[6],  p[7]));
            float g2 = fmaxf(fmaxf(p[8],  p[9]),  fmaxf(p[10], p[11]));
            float g3 = fmaxf(fmaxf(p[12], p[13]), fmaxf(p[14], p[15]));
            float g4 = fmaxf(fmaxf(p[16], p[17]), fmaxf(p[18], p[19]));
            float g5 = fmaxf(fmaxf(p[20], p[21]), fmaxf(p[22], p[23]));
            const float mx = fmaxf(fmaxf(fmaxf(g0, g1), fmaxf(g2, g3)),
                                   fmaxf(g4, g5));
            const int   sh = ((__float_as_int(mx) >> 23) & 0xff) - 127;
            const float fn = exp2i(-sh);
#pragma unroll
            for (int k = 0; k < 24; ++k) p[k] = p[k] * fn;
            K += sh;

            // Publish both rows' last-column edges at the new scale.
            const float kb = __int_as_float(K);
            eA[s % 3][t] = make_float4(n1[21] * fn, n1[22] * fn,
                                       n1[23] * fn, kb);
            eB[s % 3][t] = make_float4(p[21], p[22], p[23], kb);

            if (t == TT - 1 && i0 == NN - 1)   // i1 == NN: terminal cell
                out[0] = (float)K * 0.69314718055994531f +
                         logf(p[21] + p[22] + p[23]);
        }

        __syncthreads();

        if (ldf) {
#pragma unroll
            for (int q = 0; q < 6; ++q) cur0[q] = fut0[q];
        }
    }
}

extern "C" void kernel_launch(void* const* d_in, const int* in_sizes, int n_in,
                              void* d_out, int out_size) {
    const float* theta = (const float*)d_in[0];
    const float* A     = (const float*)d_in[1];
    if (n_in >= 2 && in_sizes[0] == 9) {  // defensive: swap if order differs
        theta = (const float*)d_in[1];
        A     = (const float*)d_in[0];
    }
    eth_kernel<<<(NN * TT) / 256, 256>>>(theta);  // exp(theta) + relayout
    ViterbiDecoder_5506148073875_kernel<<<1, TT>>>(A, (float*)d_out);
}